// round 1
// baseline (speedup 1.0000x reference)
#include <cuda_runtime.h>
#include <cstdint>
#include <cstddef>

// Problem constants
#define BDIM 4096
#define TDIM 168
#define IDIM 19
#define HDIM 64
#define GDIM 256          // 4*H
#define RPT  7            // rows per thread-group
#define RPC  28           // rows per CTA = 4 * RPT
#define NCTA 147          // ceil(4096/28)
#define NTHREADS 256

// 704 MB scratch: zx0[t][b][hu][gi]  (layer-0 input projection + biases)
__device__ float g_zx[(size_t)TDIM * BDIM * GDIM];

// ---------------- f32x2 packed-math helpers (sm_100+) ----------------
__device__ __forceinline__ void fma2(unsigned long long& d,
                                     unsigned long long a,
                                     unsigned long long b) {
    asm("fma.rn.f32x2 %0, %1, %2, %0;" : "+l"(d) : "l"(a), "l"(b));
}
__device__ __forceinline__ unsigned long long pack2(float lo, float hi) {
    unsigned long long r;
    asm("mov.b64 %0, {%1, %2};" : "=l"(r) : "f"(lo), "f"(hi));
    return r;
}
__device__ __forceinline__ float redu2(unsigned long long v) {
    float lo, hi;
    asm("mov.b64 {%0, %1}, %2;" : "=f"(lo), "=f"(hi) : "l"(v));
    return lo + hi;
}
__device__ __forceinline__ unsigned long long ld64(const float* p) {
    return *reinterpret_cast<const unsigned long long*>(p);
}

// ---------------- fast activations (branch-free, saturating) ----------------
__device__ __forceinline__ float ex2f(float x) {
    float y; asm("ex2.approx.f32 %0, %1;" : "=f"(y) : "f"(x)); return y;
}
__device__ __forceinline__ float rcpf(float x) {
    float y; asm("rcp.approx.f32 %0, %1;" : "=f"(y) : "f"(x)); return y;
}
#define LOG2E 1.4426950408889634f
__device__ __forceinline__ float sigmoidf_(float x) {
    // 1/(1+e^-x); x->-inf: ex2(inf)=inf -> rcp -> 0 ; x->+inf: -> 1
    return rcpf(1.0f + ex2f(-x * LOG2E));
}
__device__ __forceinline__ float tanhf_(float x) {
    // 1 - 2/(e^{2x}+1); saturates cleanly to +-1 without NaN
    return 1.0f - 2.0f * rcpf(ex2f(2.0f * LOG2E * x) + 1.0f);
}

// =====================================================================
// Prep kernel: g_zx[t][b][hu][gi] = sum_i x[b,t,i]*Wih0[gi*64+hu, i] + bih0 + bhh0
// grid (42, 128): TB=4 timesteps x BB=32 rows per block, 256 threads
// =====================================================================
#define TB 4
#define BB 32
__global__ void __launch_bounds__(NTHREADS) prep_kernel(
    const float* __restrict__ x,
    const float* __restrict__ Wih0,
    const float* __restrict__ bih0,
    const float* __restrict__ bhh0)
{
    __shared__ __align__(16) float sW[IDIM * GDIM];     // [i][hu][gi]
    __shared__ float sX[TB][BB][IDIM + 1];
    const int tid = threadIdx.x;
    const int t0 = blockIdx.x * TB;
    const int b0 = blockIdx.y * BB;

    // load W reordered: sW[i*256 + hu*4 + gi] = Wih0[(gi*64+hu)*19 + i]
    for (int idx = tid; idx < IDIM * GDIM; idx += NTHREADS) {
        int i  = idx >> 8;
        int c  = idx & 255;
        int hu = c >> 2, gi = c & 3;
        sW[idx] = Wih0[(gi * HDIM + hu) * IDIM + i];
    }
    // load x block
    for (int idx = tid; idx < TB * BB * IDIM; idx += NTHREADS) {
        int i  = idx % IDIM;
        int rb = idx / IDIM;
        int bb = rb % BB, tt = rb / BB;
        sX[tt][bb][i] = x[((size_t)(b0 + bb) * TDIM + (t0 + tt)) * IDIM + i];
    }
    __syncthreads();

    const int hu = tid & 63;
    const int sub = tid >> 6;             // 0..3
    float bias[4];
#pragma unroll
    for (int gi = 0; gi < 4; gi++)
        bias[gi] = bih0[gi * HDIM + hu] + bhh0[gi * HDIM + hu];
    const unsigned long long b01 = pack2(bias[0], bias[1]);
    const unsigned long long b23 = pack2(bias[2], bias[3]);

    for (int tt = 0; tt < TB; tt++) {
#pragma unroll
        for (int j = 0; j < BB / 4; j++) {   // 8 rows / thread
            const int bb = sub * (BB / 4) + j;
            unsigned long long a01 = b01, a23 = b23;
#pragma unroll
            for (int i = 0; i < IDIM; i++) {
                float xv = sX[tt][bb][i];
                unsigned long long xp = pack2(xv, xv);
                const float* wp = &sW[i * GDIM + hu * 4];
                fma2(a01, xp, ld64(wp));
                fma2(a23, xp, ld64(wp + 2));
            }
            float r0, r1, r2, r3;
            asm("mov.b64 {%0, %1}, %2;" : "=f"(r0), "=f"(r1) : "l"(a01));
            asm("mov.b64 {%0, %1}, %2;" : "=f"(r2), "=f"(r3) : "l"(a23));
            float4 out4 = make_float4(r0, r1, r2, r3);
            *reinterpret_cast<float4*>(
                &g_zx[(((size_t)(t0 + tt) * BDIM + (b0 + bb)) * HDIM + hu) * 4]) = out4;
        }
    }
}

// =====================================================================
// Main recurrent kernel: 147 CTAs x 256 threads, 28 batch rows per CTA.
// Thread t: hu = t&63 (hidden unit), rg = t>>6 -> rows rg*7 .. rg*7+6.
// Each thread computes all 4 gates (strided 64) for its (row, hu) pairs,
// so c0/c1 stay in registers and no gate exchange is needed.
// smem: W0 paired [kk][g][2] (64KB) + W1 (Wih1||Whh1, K=128) paired (128KB)
//       + h0 (28x64) + h1 (28x64)
// =====================================================================
__global__ void __launch_bounds__(NTHREADS, 1) lstm_kernel(
    const float* __restrict__ Whh0,
    const float* __restrict__ Wih1,
    const float* __restrict__ Whh1,
    const float* __restrict__ bih1,
    const float* __restrict__ bhh1,
    const float* __restrict__ Wfc,
    const float* __restrict__ bfc,
    float* __restrict__ out)
{
    extern __shared__ __align__(16) float smem[];
    float* sW0 = smem;                       // 32*256*2 = 16384 floats
    float* sW1 = sW0 + 32 * GDIM * 2;        // 64*256*2 = 32768 floats
    float* h0s = sW1 + 64 * GDIM * 2;        // 28*64
    float* h1s = h0s + RPC * HDIM;           // 28*64

    const int tid = threadIdx.x;

    // ---- stage weights into smem (k-pair interleaved layout) ----
    for (int idx = tid; idx < GDIM * 32; idx += NTHREADS) {
        int g = idx >> 5, kk = idx & 31;
        float2 v = *reinterpret_cast<const float2*>(&Whh0[g * HDIM + kk * 2]);
        sW0[(kk * GDIM + g) * 2]     = v.x;
        sW0[(kk * GDIM + g) * 2 + 1] = v.y;
    }
    for (int idx = tid; idx < GDIM * 64; idx += NTHREADS) {
        int g = idx >> 6, kk = idx & 63;
        const float* src = (kk < 32) ? &Wih1[g * HDIM + kk * 2]
                                     : &Whh1[g * HDIM + (kk - 32) * 2];
        float2 v = *reinterpret_cast<const float2*>(src);
        sW1[(kk * GDIM + g) * 2]     = v.x;
        sW1[(kk * GDIM + g) * 2 + 1] = v.y;
    }
    for (int idx = tid; idx < RPC * HDIM; idx += NTHREADS) {
        h0s[idx] = 0.0f;
        h1s[idx] = 0.0f;
    }

    const int hu = tid & 63;
    const int rg = tid >> 6;
    const int rbase = rg * RPT;
    const size_t growbase = (size_t)blockIdx.x * RPC + rbase;

    float b1v[4];
#pragma unroll
    for (int gi = 0; gi < 4; gi++)
        b1v[gi] = bih1[gi * HDIM + hu] + bhh1[gi * HDIM + hu];

    float c0[RPT], c1[RPT];
#pragma unroll
    for (int r = 0; r < RPT; r++) { c0[r] = 0.0f; c1[r] = 0.0f; }

    __syncthreads();

    for (int t = 0; t < TDIM; t++) {
        // ================= layer 0 =================
        // issue zx loads early; consumed only after the GEMM (latency hidden)
        float4 zx[RPT];
#pragma unroll
        for (int r = 0; r < RPT; r++) {
            size_t grow = growbase + r;
            if (grow < BDIM)
                zx[r] = *reinterpret_cast<const float4*>(
                    &g_zx[(((size_t)t * BDIM + grow) * HDIM + hu) * 4]);
            else
                zx[r] = make_float4(0.f, 0.f, 0.f, 0.f);
        }

        unsigned long long acc[RPT][4];
#pragma unroll
        for (int r = 0; r < RPT; r++)
#pragma unroll
            for (int gi = 0; gi < 4; gi++) acc[r][gi] = 0ULL;

#pragma unroll 8
        for (int kk = 0; kk < 32; kk++) {
            unsigned long long w0 = ld64(&sW0[(kk * GDIM + hu) * 2]);
            unsigned long long w1 = ld64(&sW0[(kk * GDIM + 64 + hu) * 2]);
            unsigned long long w2 = ld64(&sW0[(kk * GDIM + 128 + hu) * 2]);
            unsigned long long w3 = ld64(&sW0[(kk * GDIM + 192 + hu) * 2]);
#pragma unroll
            for (int r = 0; r < RPT; r++) {
                unsigned long long hp = ld64(&h0s[(rbase + r) * HDIM + kk * 2]);
                fma2(acc[r][0], hp, w0);
                fma2(acc[r][1], hp, w1);
                fma2(acc[r][2], hp, w2);
                fma2(acc[r][3], hp, w3);
            }
        }

        float hnew0[RPT];
#pragma unroll
        for (int r = 0; r < RPT; r++) {
            float zi = redu2(acc[r][0]) + zx[r].x;
            float zf = redu2(acc[r][1]) + zx[r].y;
            float zg = redu2(acc[r][2]) + zx[r].z;
            float zo = redu2(acc[r][3]) + zx[r].w;
            float ig = sigmoidf_(zi);
            float fg = sigmoidf_(zf);
            float gg = tanhf_(zg);
            float og = sigmoidf_(zo);
            float c = fg * c0[r] + ig * gg;
            c0[r] = c;
            hnew0[r] = og * tanhf_(c);
        }
        __syncthreads();          // everyone done reading h0s (old)
#pragma unroll
        for (int r = 0; r < RPT; r++) h0s[(rbase + r) * HDIM + hu] = hnew0[r];
        __syncthreads();          // h0s (new) visible

        // ================= layer 1 (K = 128: [h0_new ; h1_old]) =================
#pragma unroll
        for (int r = 0; r < RPT; r++)
#pragma unroll
            for (int gi = 0; gi < 4; gi++) acc[r][gi] = 0ULL;

#pragma unroll 8
        for (int kk = 0; kk < 32; kk++) {
            unsigned long long w0 = ld64(&sW1[(kk * GDIM + hu) * 2]);
            unsigned long long w1 = ld64(&sW1[(kk * GDIM + 64 + hu) * 2]);
            unsigned long long w2 = ld64(&sW1[(kk * GDIM + 128 + hu) * 2]);
            unsigned long long w3 = ld64(&sW1[(kk * GDIM + 192 + hu) * 2]);
#pragma unroll
            for (int r = 0; r < RPT; r++) {
                unsigned long long hp = ld64(&h0s[(rbase + r) * HDIM + kk * 2]);
                fma2(acc[r][0], hp, w0);
                fma2(acc[r][1], hp, w1);
                fma2(acc[r][2], hp, w2);
                fma2(acc[r][3], hp, w3);
            }
        }
#pragma unroll 8
        for (int kk = 32; kk < 64; kk++) {
            unsigned long long w0 = ld64(&sW1[(kk * GDIM + hu) * 2]);
            unsigned long long w1 = ld64(&sW1[(kk * GDIM + 64 + hu) * 2]);
            unsigned long long w2 = ld64(&sW1[(kk * GDIM + 128 + hu) * 2]);
            unsigned long long w3 = ld64(&sW1[(kk * GDIM + 192 + hu) * 2]);
#pragma unroll
            for (int r = 0; r < RPT; r++) {
                unsigned long long hp = ld64(&h1s[(rbase + r) * HDIM + (kk - 32) * 2]);
                fma2(acc[r][0], hp, w0);
                fma2(acc[r][1], hp, w1);
                fma2(acc[r][2], hp, w2);
                fma2(acc[r][3], hp, w3);
            }
        }

        float hnew1[RPT];
#pragma unroll
        for (int r = 0; r < RPT; r++) {
            float zi = redu2(acc[r][0]) + b1v[0];
            float zf = redu2(acc[r][1]) + b1v[1];
            float zg = redu2(acc[r][2]) + b1v[2];
            float zo = redu2(acc[r][3]) + b1v[3];
            float ig = sigmoidf_(zi);
            float fg = sigmoidf_(zf);
            float gg = tanhf_(zg);
            float og = sigmoidf_(zo);
            float c = fg * c1[r] + ig * gg;
            c1[r] = c;
            hnew1[r] = og * tanhf_(c);
        }
        __syncthreads();          // everyone done reading h1s (old)
#pragma unroll
        for (int r = 0; r < RPT; r++) h1s[(rbase + r) * HDIM + hu] = hnew1[r];
        __syncthreads();          // h1s (new) visible
    }

    // ---- final FC on last hidden state ----
    if (tid < RPC) {
        size_t grow = (size_t)blockIdx.x * RPC + tid;
        if (grow < BDIM) {
            float s = bfc[0];
#pragma unroll 8
            for (int k = 0; k < HDIM; k++) s += h1s[tid * HDIM + k] * Wfc[k];
            out[grow] = s;
        }
    }
}

// =====================================================================
extern "C" void kernel_launch(void* const* d_in, const int* in_sizes, int n_in,
                              void* d_out, int out_size)
{
    const float* x    = (const float*)d_in[0];
    const float* Wih0 = (const float*)d_in[1];
    const float* Whh0 = (const float*)d_in[2];
    const float* bih0 = (const float*)d_in[3];
    const float* bhh0 = (const float*)d_in[4];
    const float* Wih1 = (const float*)d_in[5];
    const float* Whh1 = (const float*)d_in[6];
    const float* bih1 = (const float*)d_in[7];
    const float* bhh1 = (const float*)d_in[8];
    const float* Wfc  = (const float*)d_in[9];
    const float* bfc  = (const float*)d_in[10];
    float* out = (float*)d_out;

    const int smem_bytes = (32 * GDIM * 2 + 64 * GDIM * 2 + 2 * RPC * HDIM) * 4;
    cudaFuncSetAttribute(lstm_kernel,
                         cudaFuncAttributeMaxDynamicSharedMemorySize, smem_bytes);

    dim3 pgrid(TDIM / TB, BDIM / BB);
    prep_kernel<<<pgrid, NTHREADS>>>(x, Wih0, bih0, bhh0);
    lstm_kernel<<<NCTA, NTHREADS, smem_bytes>>>(Whh0, Wih1, Whh1, bih1, bhh1,
                                                Wfc, bfc, out);
}

// round 2
// speedup vs baseline: 1.0012x; 1.0012x over previous
#include <cuda_runtime.h>
#include <cstdint>
#include <cstddef>

// Problem constants
#define BDIM 4096
#define TDIM 168
#define IDIM 19
#define HDIM 64
#define GDIM 256          // 4*H
#define RPT  7            // rows per thread-group
#define RPC  28           // rows per CTA = 4 * RPT
#define NCTA 147          // ceil(4096/28)
#define NTHREADS 256

// 704 MB scratch: zx0[t][b][hu][gi]  (layer-0 input projection + biases)
__device__ float g_zx[(size_t)TDIM * BDIM * GDIM];

// ---------------- f32x2 packed-math helpers (sm_100+) ----------------
__device__ __forceinline__ void fma2(unsigned long long& d,
                                     unsigned long long a,
                                     unsigned long long b) {
    asm("fma.rn.f32x2 %0, %1, %2, %0;" : "+l"(d) : "l"(a), "l"(b));
}
__device__ __forceinline__ unsigned long long pack2(float lo, float hi) {
    unsigned long long r;
    asm("mov.b64 %0, {%1, %2};" : "=l"(r) : "f"(lo), "f"(hi));
    return r;
}
__device__ __forceinline__ float redu2(unsigned long long v) {
    float lo, hi;
    asm("mov.b64 {%0, %1}, %2;" : "=f"(lo), "=f"(hi) : "l"(v));
    return lo + hi;
}
__device__ __forceinline__ unsigned long long ld64(const float* p) {
    return *reinterpret_cast<const unsigned long long*>(p);
}

// ---------------- fast activations (branch-free, saturating) ----------------
__device__ __forceinline__ float ex2f(float x) {
    float y; asm("ex2.approx.f32 %0, %1;" : "=f"(y) : "f"(x)); return y;
}
__device__ __forceinline__ float rcpf(float x) {
    float y; asm("rcp.approx.f32 %0, %1;" : "=f"(y) : "f"(x)); return y;
}
#define LOG2E 1.4426950408889634f
__device__ __forceinline__ float sigmoidf_(float x) {
    // 1/(1+e^-x); x->-inf: ex2(inf)=inf -> rcp -> 0 ; x->+inf: -> 1
    return rcpf(1.0f + ex2f(-x * LOG2E));
}
__device__ __forceinline__ float tanhf_(float x) {
    // 1 - 2/(e^{2x}+1); saturates cleanly to +-1 without NaN
    return 1.0f - 2.0f * rcpf(ex2f(2.0f * LOG2E * x) + 1.0f);
}

// =====================================================================
// Prep kernel: g_zx[t][b][hu][gi] = sum_i x[b,t,i]*Wih0[gi*64+hu, i] + bih0 + bhh0
// grid (42, 128): TB=4 timesteps x BB=32 rows per block, 256 threads
// =====================================================================
#define TB 4
#define BB 32
__global__ void __launch_bounds__(NTHREADS) prep_kernel(
    const float* __restrict__ x,
    const float* __restrict__ Wih0,
    const float* __restrict__ bih0,
    const float* __restrict__ bhh0)
{
    __shared__ __align__(16) float sW[IDIM * GDIM];     // [i][hu][gi]
    __shared__ float sX[TB][BB][IDIM + 1];
    const int tid = threadIdx.x;
    const int t0 = blockIdx.x * TB;
    const int b0 = blockIdx.y * BB;

    // load W reordered: sW[i*256 + hu*4 + gi] = Wih0[(gi*64+hu)*19 + i]
    for (int idx = tid; idx < IDIM * GDIM; idx += NTHREADS) {
        int i  = idx >> 8;
        int c  = idx & 255;
        int hu = c >> 2, gi = c & 3;
        sW[idx] = Wih0[(gi * HDIM + hu) * IDIM + i];
    }
    // load x block
    for (int idx = tid; idx < TB * BB * IDIM; idx += NTHREADS) {
        int i  = idx % IDIM;
        int rb = idx / IDIM;
        int bb = rb % BB, tt = rb / BB;
        sX[tt][bb][i] = x[((size_t)(b0 + bb) * TDIM + (t0 + tt)) * IDIM + i];
    }
    __syncthreads();

    const int hu = tid & 63;
    const int sub = tid >> 6;             // 0..3
    float bias[4];
#pragma unroll
    for (int gi = 0; gi < 4; gi++)
        bias[gi] = bih0[gi * HDIM + hu] + bhh0[gi * HDIM + hu];
    const unsigned long long b01 = pack2(bias[0], bias[1]);
    const unsigned long long b23 = pack2(bias[2], bias[3]);

    for (int tt = 0; tt < TB; tt++) {
#pragma unroll
        for (int j = 0; j < BB / 4; j++) {   // 8 rows / thread
            const int bb = sub * (BB / 4) + j;
            unsigned long long a01 = b01, a23 = b23;
#pragma unroll
            for (int i = 0; i < IDIM; i++) {
                float xv = sX[tt][bb][i];
                unsigned long long xp = pack2(xv, xv);
                const float* wp = &sW[i * GDIM + hu * 4];
                fma2(a01, xp, ld64(wp));
                fma2(a23, xp, ld64(wp + 2));
            }
            float r0, r1, r2, r3;
            asm("mov.b64 {%0, %1}, %2;" : "=f"(r0), "=f"(r1) : "l"(a01));
            asm("mov.b64 {%0, %1}, %2;" : "=f"(r2), "=f"(r3) : "l"(a23));
            float4 out4 = make_float4(r0, r1, r2, r3);
            *reinterpret_cast<float4*>(
                &g_zx[(((size_t)(t0 + tt) * BDIM + (b0 + bb)) * HDIM + hu) * 4]) = out4;
        }
    }
}

// =====================================================================
// Main recurrent kernel: 147 CTAs x 256 threads, 28 batch rows per CTA.
// Thread t: hu = t&63 (hidden unit), rg = t>>6 -> rows rg*7 .. rg*7+6.
// Each thread computes all 4 gates (strided 64) for its (row, hu) pairs,
// so c0/c1 stay in registers and no gate exchange is needed.
// smem: W0 paired [kk][g][2] (64KB) + W1 (Wih1||Whh1, K=128) paired (128KB)
//       + h0 (28x64) + h1 (28x64)
// =====================================================================
__global__ void __launch_bounds__(NTHREADS, 1) lstm_kernel(
    const float* __restrict__ Whh0,
    const float* __restrict__ Wih1,
    const float* __restrict__ Whh1,
    const float* __restrict__ bih1,
    const float* __restrict__ bhh1,
    const float* __restrict__ Wfc,
    const float* __restrict__ bfc,
    float* __restrict__ out)
{
    extern __shared__ __align__(16) float smem[];
    float* sW0 = smem;                       // 32*256*2 = 16384 floats
    float* sW1 = sW0 + 32 * GDIM * 2;        // 64*256*2 = 32768 floats
    float* h0s = sW1 + 64 * GDIM * 2;        // 28*64
    float* h1s = h0s + RPC * HDIM;           // 28*64

    const int tid = threadIdx.x;

    // ---- stage weights into smem (k-pair interleaved layout) ----
    for (int idx = tid; idx < GDIM * 32; idx += NTHREADS) {
        int g = idx >> 5, kk = idx & 31;
        float2 v = *reinterpret_cast<const float2*>(&Whh0[g * HDIM + kk * 2]);
        sW0[(kk * GDIM + g) * 2]     = v.x;
        sW0[(kk * GDIM + g) * 2 + 1] = v.y;
    }
    for (int idx = tid; idx < GDIM * 64; idx += NTHREADS) {
        int g = idx >> 6, kk = idx & 63;
        const float* src = (kk < 32) ? &Wih1[g * HDIM + kk * 2]
                                     : &Whh1[g * HDIM + (kk - 32) * 2];
        float2 v = *reinterpret_cast<const float2*>(src);
        sW1[(kk * GDIM + g) * 2]     = v.x;
        sW1[(kk * GDIM + g) * 2 + 1] = v.y;
    }
    for (int idx = tid; idx < RPC * HDIM; idx += NTHREADS) {
        h0s[idx] = 0.0f;
        h1s[idx] = 0.0f;
    }

    const int hu = tid & 63;
    const int rg = tid >> 6;
    const int rbase = rg * RPT;
    const size_t growbase = (size_t)blockIdx.x * RPC + rbase;

    float b1v[4];
#pragma unroll
    for (int gi = 0; gi < 4; gi++)
        b1v[gi] = bih1[gi * HDIM + hu] + bhh1[gi * HDIM + hu];

    float c0[RPT], c1[RPT];
#pragma unroll
    for (int r = 0; r < RPT; r++) { c0[r] = 0.0f; c1[r] = 0.0f; }

    __syncthreads();

    for (int t = 0; t < TDIM; t++) {
        // ================= layer 0 =================
        // issue zx loads early; consumed only after the GEMM (latency hidden)
        float4 zx[RPT];
#pragma unroll
        for (int r = 0; r < RPT; r++) {
            size_t grow = growbase + r;
            if (grow < BDIM)
                zx[r] = *reinterpret_cast<const float4*>(
                    &g_zx[(((size_t)t * BDIM + grow) * HDIM + hu) * 4]);
            else
                zx[r] = make_float4(0.f, 0.f, 0.f, 0.f);
        }

        unsigned long long acc[RPT][4];
#pragma unroll
        for (int r = 0; r < RPT; r++)
#pragma unroll
            for (int gi = 0; gi < 4; gi++) acc[r][gi] = 0ULL;

#pragma unroll 8
        for (int kk = 0; kk < 32; kk++) {
            unsigned long long w0 = ld64(&sW0[(kk * GDIM + hu) * 2]);
            unsigned long long w1 = ld64(&sW0[(kk * GDIM + 64 + hu) * 2]);
            unsigned long long w2 = ld64(&sW0[(kk * GDIM + 128 + hu) * 2]);
            unsigned long long w3 = ld64(&sW0[(kk * GDIM + 192 + hu) * 2]);
#pragma unroll
            for (int r = 0; r < RPT; r++) {
                unsigned long long hp = ld64(&h0s[(rbase + r) * HDIM + kk * 2]);
                fma2(acc[r][0], hp, w0);
                fma2(acc[r][1], hp, w1);
                fma2(acc[r][2], hp, w2);
                fma2(acc[r][3], hp, w3);
            }
        }

        float hnew0[RPT];
#pragma unroll
        for (int r = 0; r < RPT; r++) {
            float zi = redu2(acc[r][0]) + zx[r].x;
            float zf = redu2(acc[r][1]) + zx[r].y;
            float zg = redu2(acc[r][2]) + zx[r].z;
            float zo = redu2(acc[r][3]) + zx[r].w;
            float ig = sigmoidf_(zi);
            float fg = sigmoidf_(zf);
            float gg = tanhf_(zg);
            float og = sigmoidf_(zo);
            float c = fg * c0[r] + ig * gg;
            c0[r] = c;
            hnew0[r] = og * tanhf_(c);
        }
        __syncthreads();          // everyone done reading h0s (old)
#pragma unroll
        for (int r = 0; r < RPT; r++) h0s[(rbase + r) * HDIM + hu] = hnew0[r];
        __syncthreads();          // h0s (new) visible

        // ================= layer 1 (K = 128: [h0_new ; h1_old]) =================
#pragma unroll
        for (int r = 0; r < RPT; r++)
#pragma unroll
            for (int gi = 0; gi < 4; gi++) acc[r][gi] = 0ULL;

#pragma unroll 8
        for (int kk = 0; kk < 32; kk++) {
            unsigned long long w0 = ld64(&sW1[(kk * GDIM + hu) * 2]);
            unsigned long long w1 = ld64(&sW1[(kk * GDIM + 64 + hu) * 2]);
            unsigned long long w2 = ld64(&sW1[(kk * GDIM + 128 + hu) * 2]);
            unsigned long long w3 = ld64(&sW1[(kk * GDIM + 192 + hu) * 2]);
#pragma unroll
            for (int r = 0; r < RPT; r++) {
                unsigned long long hp = ld64(&h0s[(rbase + r) * HDIM + kk * 2]);
                fma2(acc[r][0], hp, w0);
                fma2(acc[r][1], hp, w1);
                fma2(acc[r][2], hp, w2);
                fma2(acc[r][3], hp, w3);
            }
        }
#pragma unroll 8
        for (int kk = 32; kk < 64; kk++) {
            unsigned long long w0 = ld64(&sW1[(kk * GDIM + hu) * 2]);
            unsigned long long w1 = ld64(&sW1[(kk * GDIM + 64 + hu) * 2]);
            unsigned long long w2 = ld64(&sW1[(kk * GDIM + 128 + hu) * 2]);
            unsigned long long w3 = ld64(&sW1[(kk * GDIM + 192 + hu) * 2]);
#pragma unroll
            for (int r = 0; r < RPT; r++) {
                unsigned long long hp = ld64(&h1s[(rbase + r) * HDIM + (kk - 32) * 2]);
                fma2(acc[r][0], hp, w0);
                fma2(acc[r][1], hp, w1);
                fma2(acc[r][2], hp, w2);
                fma2(acc[r][3], hp, w3);
            }
        }

        float hnew1[RPT];
#pragma unroll
        for (int r = 0; r < RPT; r++) {
            float zi = redu2(acc[r][0]) + b1v[0];
            float zf = redu2(acc[r][1]) + b1v[1];
            float zg = redu2(acc[r][2]) + b1v[2];
            float zo = redu2(acc[r][3]) + b1v[3];
            float ig = sigmoidf_(zi);
            float fg = sigmoidf_(zf);
            float gg = tanhf_(zg);
            float og = sigmoidf_(zo);
            float c = fg * c1[r] + ig * gg;
            c1[r] = c;
            hnew1[r] = og * tanhf_(c);
        }
        __syncthreads();          // everyone done reading h1s (old)
#pragma unroll
        for (int r = 0; r < RPT; r++) h1s[(rbase + r) * HDIM + hu] = hnew1[r];
        __syncthreads();          // h1s (new) visible
    }

    // ---- final FC on last hidden state ----
    if (tid < RPC) {
        size_t grow = (size_t)blockIdx.x * RPC + tid;
        if (grow < BDIM) {
            float s = bfc[0];
#pragma unroll 8
            for (int k = 0; k < HDIM; k++) s += h1s[tid * HDIM + k] * Wfc[k];
            out[grow] = s;
        }
    }
}

// =====================================================================
extern "C" void kernel_launch(void* const* d_in, const int* in_sizes, int n_in,
                              void* d_out, int out_size)
{
    const float* x    = (const float*)d_in[0];
    const float* Wih0 = (const float*)d_in[1];
    const float* Whh0 = (const float*)d_in[2];
    const float* bih0 = (const float*)d_in[3];
    const float* bhh0 = (const float*)d_in[4];
    const float* Wih1 = (const float*)d_in[5];
    const float* Whh1 = (const float*)d_in[6];
    const float* bih1 = (const float*)d_in[7];
    const float* bhh1 = (const float*)d_in[8];
    const float* Wfc  = (const float*)d_in[9];
    const float* bfc  = (const float*)d_in[10];
    float* out = (float*)d_out;

    const int smem_bytes = (32 * GDIM * 2 + 64 * GDIM * 2 + 2 * RPC * HDIM) * 4;
    cudaFuncSetAttribute(lstm_kernel,
                         cudaFuncAttributeMaxDynamicSharedMemorySize, smem_bytes);

    dim3 pgrid(TDIM / TB, BDIM / BB);
    prep_kernel<<<pgrid, NTHREADS>>>(x, Wih0, bih0, bhh0);
    lstm_kernel<<<NCTA, NTHREADS, smem_bytes>>>(Whh0, Wih1, Whh1, bih1, bhh1,
                                                Wfc, bfc, out);
}

// round 3
// speedup vs baseline: 1.0019x; 1.0007x over previous
#include <cuda_runtime.h>
#include <cstdint>
#include <cstddef>

// Problem constants
#define BDIM 4096
#define TDIM 168
#define IDIM 19
#define HDIM 64
#define GDIM 256          // 4*H
#define RPT  7            // rows per thread-group
#define RPC  28           // rows per CTA = 4 * RPT
#define NCTA 147          // ceil(4096/28)
#define NTHREADS 256

// 704 MB scratch: zx0[t][b][hu][gi]  (layer-0 input projection + biases)
__device__ float g_zx[(size_t)TDIM * BDIM * GDIM];

// ---------------- f32x2 packed-math helpers (sm_100+) ----------------
__device__ __forceinline__ void fma2(unsigned long long& d,
                                     unsigned long long a,
                                     unsigned long long b) {
    asm("fma.rn.f32x2 %0, %1, %2, %0;" : "+l"(d) : "l"(a), "l"(b));
}
__device__ __forceinline__ unsigned long long pack2(float lo, float hi) {
    unsigned long long r;
    asm("mov.b64 %0, {%1, %2};" : "=l"(r) : "f"(lo), "f"(hi));
    return r;
}
__device__ __forceinline__ float redu2(unsigned long long v) {
    float lo, hi;
    asm("mov.b64 {%0, %1}, %2;" : "=f"(lo), "=f"(hi) : "l"(v));
    return lo + hi;
}
__device__ __forceinline__ unsigned long long ld64(const float* p) {
    return *reinterpret_cast<const unsigned long long*>(p);
}

// ---------------- fast activations (branch-free, saturating) ----------------
__device__ __forceinline__ float ex2f(float x) {
    float y; asm("ex2.approx.f32 %0, %1;" : "=f"(y) : "f"(x)); return y;
}
__device__ __forceinline__ float rcpf(float x) {
    float y; asm("rcp.approx.f32 %0, %1;" : "=f"(y) : "f"(x)); return y;
}
#define LOG2E 1.4426950408889634f
__device__ __forceinline__ float sigmoidf_(float x) {
    // 1/(1+e^-x); x->-inf: ex2(inf)=inf -> rcp -> 0 ; x->+inf: -> 1
    return rcpf(1.0f + ex2f(-x * LOG2E));
}
__device__ __forceinline__ float tanhf_(float x) {
    // 1 - 2/(e^{2x}+1); saturates cleanly to +-1 without NaN
    return 1.0f - 2.0f * rcpf(ex2f(2.0f * LOG2E * x) + 1.0f);
}

// =====================================================================
// Prep kernel: g_zx[t][b][hu][gi] = sum_i x[b,t,i]*Wih0[gi*64+hu, i] + bih0 + bhh0
// grid (42, 128): TB=4 timesteps x BB=32 rows per block, 256 threads
// =====================================================================
#define TB 4
#define BB 32
__global__ void __launch_bounds__(NTHREADS) prep_kernel(
    const float* __restrict__ x,
    const float* __restrict__ Wih0,
    const float* __restrict__ bih0,
    const float* __restrict__ bhh0)
{
    __shared__ __align__(16) float sW[IDIM * GDIM];     // [i][hu][gi]
    __shared__ float sX[TB][BB][IDIM + 1];
    const int tid = threadIdx.x;
    const int t0 = blockIdx.x * TB;
    const int b0 = blockIdx.y * BB;

    // load W reordered: sW[i*256 + hu*4 + gi] = Wih0[(gi*64+hu)*19 + i]
    for (int idx = tid; idx < IDIM * GDIM; idx += NTHREADS) {
        int i  = idx >> 8;
        int c  = idx & 255;
        int hu = c >> 2, gi = c & 3;
        sW[idx] = Wih0[(gi * HDIM + hu) * IDIM + i];
    }
    // load x block
    for (int idx = tid; idx < TB * BB * IDIM; idx += NTHREADS) {
        int i  = idx % IDIM;
        int rb = idx / IDIM;
        int bb = rb % BB, tt = rb / BB;
        sX[tt][bb][i] = x[((size_t)(b0 + bb) * TDIM + (t0 + tt)) * IDIM + i];
    }
    __syncthreads();

    const int hu = tid & 63;
    const int sub = tid >> 6;             // 0..3
    float bias[4];
#pragma unroll
    for (int gi = 0; gi < 4; gi++)
        bias[gi] = bih0[gi * HDIM + hu] + bhh0[gi * HDIM + hu];
    const unsigned long long b01 = pack2(bias[0], bias[1]);
    const unsigned long long b23 = pack2(bias[2], bias[3]);

    for (int tt = 0; tt < TB; tt++) {
#pragma unroll
        for (int j = 0; j < BB / 4; j++) {   // 8 rows / thread
            const int bb = sub * (BB / 4) + j;
            unsigned long long a01 = b01, a23 = b23;
#pragma unroll
            for (int i = 0; i < IDIM; i++) {
                float xv = sX[tt][bb][i];
                unsigned long long xp = pack2(xv, xv);
                const float* wp = &sW[i * GDIM + hu * 4];
                fma2(a01, xp, ld64(wp));
                fma2(a23, xp, ld64(wp + 2));
            }
            float r0, r1, r2, r3;
            asm("mov.b64 {%0, %1}, %2;" : "=f"(r0), "=f"(r1) : "l"(a01));
            asm("mov.b64 {%0, %1}, %2;" : "=f"(r2), "=f"(r3) : "l"(a23));
            float4 out4 = make_float4(r0, r1, r2, r3);
            *reinterpret_cast<float4*>(
                &g_zx[(((size_t)(t0 + tt) * BDIM + (b0 + bb)) * HDIM + hu) * 4]) = out4;
        }
    }
}

// =====================================================================
// Main recurrent kernel: 147 CTAs x 256 threads, 28 batch rows per CTA.
// Thread t: hu = t&63 (hidden unit), rg = t>>6 -> rows rg*7 .. rg*7+6.
// Each thread computes all 4 gates (strided 64) for its (row, hu) pairs,
// so c0/c1 stay in registers and no gate exchange is needed.
// smem: W0 paired [kk][g][2] (64KB) + W1 (Wih1||Whh1, K=128) paired (128KB)
//       + h0 (28x64) + h1 (28x64)
// =====================================================================
__global__ void __launch_bounds__(NTHREADS, 1) lstm_kernel(
    const float* __restrict__ Whh0,
    const float* __restrict__ Wih1,
    const float* __restrict__ Whh1,
    const float* __restrict__ bih1,
    const float* __restrict__ bhh1,
    const float* __restrict__ Wfc,
    const float* __restrict__ bfc,
    float* __restrict__ out)
{
    extern __shared__ __align__(16) float smem[];
    float* sW0 = smem;                       // 32*256*2 = 16384 floats
    float* sW1 = sW0 + 32 * GDIM * 2;        // 64*256*2 = 32768 floats
    float* h0s = sW1 + 64 * GDIM * 2;        // 28*64
    float* h1s = h0s + RPC * HDIM;           // 28*64

    const int tid = threadIdx.x;

    // ---- stage weights into smem (k-pair interleaved layout) ----
    for (int idx = tid; idx < GDIM * 32; idx += NTHREADS) {
        int g = idx >> 5, kk = idx & 31;
        float2 v = *reinterpret_cast<const float2*>(&Whh0[g * HDIM + kk * 2]);
        sW0[(kk * GDIM + g) * 2]     = v.x;
        sW0[(kk * GDIM + g) * 2 + 1] = v.y;
    }
    for (int idx = tid; idx < GDIM * 64; idx += NTHREADS) {
        int g = idx >> 6, kk = idx & 63;
        const float* src = (kk < 32) ? &Wih1[g * HDIM + kk * 2]
                                     : &Whh1[g * HDIM + (kk - 32) * 2];
        float2 v = *reinterpret_cast<const float2*>(src);
        sW1[(kk * GDIM + g) * 2]     = v.x;
        sW1[(kk * GDIM + g) * 2 + 1] = v.y;
    }
    for (int idx = tid; idx < RPC * HDIM; idx += NTHREADS) {
        h0s[idx] = 0.0f;
        h1s[idx] = 0.0f;
    }

    const int hu = tid & 63;
    const int rg = tid >> 6;
    const int rbase = rg * RPT;
    const size_t growbase = (size_t)blockIdx.x * RPC + rbase;

    float b1v[4];
#pragma unroll
    for (int gi = 0; gi < 4; gi++)
        b1v[gi] = bih1[gi * HDIM + hu] + bhh1[gi * HDIM + hu];

    float c0[RPT], c1[RPT];
#pragma unroll
    for (int r = 0; r < RPT; r++) { c0[r] = 0.0f; c1[r] = 0.0f; }

    __syncthreads();

    for (int t = 0; t < TDIM; t++) {
        // ================= layer 0 =================
        // issue zx loads early; consumed only after the GEMM (latency hidden)
        float4 zx[RPT];
#pragma unroll
        for (int r = 0; r < RPT; r++) {
            size_t grow = growbase + r;
            if (grow < BDIM)
                zx[r] = *reinterpret_cast<const float4*>(
                    &g_zx[(((size_t)t * BDIM + grow) * HDIM + hu) * 4]);
            else
                zx[r] = make_float4(0.f, 0.f, 0.f, 0.f);
        }

        unsigned long long acc[RPT][4];
#pragma unroll
        for (int r = 0; r < RPT; r++)
#pragma unroll
            for (int gi = 0; gi < 4; gi++) acc[r][gi] = 0ULL;

#pragma unroll 8
        for (int kk = 0; kk < 32; kk++) {
            unsigned long long w0 = ld64(&sW0[(kk * GDIM + hu) * 2]);
            unsigned long long w1 = ld64(&sW0[(kk * GDIM + 64 + hu) * 2]);
            unsigned long long w2 = ld64(&sW0[(kk * GDIM + 128 + hu) * 2]);
            unsigned long long w3 = ld64(&sW0[(kk * GDIM + 192 + hu) * 2]);
#pragma unroll
            for (int r = 0; r < RPT; r++) {
                unsigned long long hp = ld64(&h0s[(rbase + r) * HDIM + kk * 2]);
                fma2(acc[r][0], hp, w0);
                fma2(acc[r][1], hp, w1);
                fma2(acc[r][2], hp, w2);
                fma2(acc[r][3], hp, w3);
            }
        }

        float hnew0[RPT];
#pragma unroll
        for (int r = 0; r < RPT; r++) {
            float zi = redu2(acc[r][0]) + zx[r].x;
            float zf = redu2(acc[r][1]) + zx[r].y;
            float zg = redu2(acc[r][2]) + zx[r].z;
            float zo = redu2(acc[r][3]) + zx[r].w;
            float ig = sigmoidf_(zi);
            float fg = sigmoidf_(zf);
            float gg = tanhf_(zg);
            float og = sigmoidf_(zo);
            float c = fg * c0[r] + ig * gg;
            c0[r] = c;
            hnew0[r] = og * tanhf_(c);
        }
        __syncthreads();          // everyone done reading h0s (old)
#pragma unroll
        for (int r = 0; r < RPT; r++) h0s[(rbase + r) * HDIM + hu] = hnew0[r];
        __syncthreads();          // h0s (new) visible

        // ================= layer 1 (K = 128: [h0_new ; h1_old]) =================
#pragma unroll
        for (int r = 0; r < RPT; r++)
#pragma unroll
            for (int gi = 0; gi < 4; gi++) acc[r][gi] = 0ULL;

#pragma unroll 8
        for (int kk = 0; kk < 32; kk++) {
            unsigned long long w0 = ld64(&sW1[(kk * GDIM + hu) * 2]);
            unsigned long long w1 = ld64(&sW1[(kk * GDIM + 64 + hu) * 2]);
            unsigned long long w2 = ld64(&sW1[(kk * GDIM + 128 + hu) * 2]);
            unsigned long long w3 = ld64(&sW1[(kk * GDIM + 192 + hu) * 2]);
#pragma unroll
            for (int r = 0; r < RPT; r++) {
                unsigned long long hp = ld64(&h0s[(rbase + r) * HDIM + kk * 2]);
                fma2(acc[r][0], hp, w0);
                fma2(acc[r][1], hp, w1);
                fma2(acc[r][2], hp, w2);
                fma2(acc[r][3], hp, w3);
            }
        }
#pragma unroll 8
        for (int kk = 32; kk < 64; kk++) {
            unsigned long long w0 = ld64(&sW1[(kk * GDIM + hu) * 2]);
            unsigned long long w1 = ld64(&sW1[(kk * GDIM + 64 + hu) * 2]);
            unsigned long long w2 = ld64(&sW1[(kk * GDIM + 128 + hu) * 2]);
            unsigned long long w3 = ld64(&sW1[(kk * GDIM + 192 + hu) * 2]);
#pragma unroll
            for (int r = 0; r < RPT; r++) {
                unsigned long long hp = ld64(&h1s[(rbase + r) * HDIM + (kk - 32) * 2]);
                fma2(acc[r][0], hp, w0);
                fma2(acc[r][1], hp, w1);
                fma2(acc[r][2], hp, w2);
                fma2(acc[r][3], hp, w3);
            }
        }

        float hnew1[RPT];
#pragma unroll
        for (int r = 0; r < RPT; r++) {
            float zi = redu2(acc[r][0]) + b1v[0];
            float zf = redu2(acc[r][1]) + b1v[1];
            float zg = redu2(acc[r][2]) + b1v[2];
            float zo = redu2(acc[r][3]) + b1v[3];
            float ig = sigmoidf_(zi);
            float fg = sigmoidf_(zf);
            float gg = tanhf_(zg);
            float og = sigmoidf_(zo);
            float c = fg * c1[r] + ig * gg;
            c1[r] = c;
            hnew1[r] = og * tanhf_(c);
        }
        __syncthreads();          // everyone done reading h1s (old)
#pragma unroll
        for (int r = 0; r < RPT; r++) h1s[(rbase + r) * HDIM + hu] = hnew1[r];
        __syncthreads();          // h1s (new) visible
    }

    // ---- final FC on last hidden state ----
    if (tid < RPC) {
        size_t grow = (size_t)blockIdx.x * RPC + tid;
        if (grow < BDIM) {
            float s = bfc[0];
#pragma unroll 8
            for (int k = 0; k < HDIM; k++) s += h1s[tid * HDIM + k] * Wfc[k];
            out[grow] = s;
        }
    }
}

// =====================================================================
extern "C" void kernel_launch(void* const* d_in, const int* in_sizes, int n_in,
                              void* d_out, int out_size)
{
    const float* x    = (const float*)d_in[0];
    const float* Wih0 = (const float*)d_in[1];
    const float* Whh0 = (const float*)d_in[2];
    const float* bih0 = (const float*)d_in[3];
    const float* bhh0 = (const float*)d_in[4];
    const float* Wih1 = (const float*)d_in[5];
    const float* Whh1 = (const float*)d_in[6];
    const float* bih1 = (const float*)d_in[7];
    const float* bhh1 = (const float*)d_in[8];
    const float* Wfc  = (const float*)d_in[9];
    const float* bfc  = (const float*)d_in[10];
    float* out = (float*)d_out;

    const int smem_bytes = (32 * GDIM * 2 + 64 * GDIM * 2 + 2 * RPC * HDIM) * 4;
    cudaFuncSetAttribute(lstm_kernel,
                         cudaFuncAttributeMaxDynamicSharedMemorySize, smem_bytes);

    dim3 pgrid(TDIM / TB, BDIM / BB);
    prep_kernel<<<pgrid, NTHREADS>>>(x, Wih0, bih0, bhh0);
    lstm_kernel<<<NCTA, NTHREADS, smem_bytes>>>(Whh0, Wih1, Whh1, bih1, bhh1,
                                                Wfc, bfc, out);
}